// round 13
// baseline (speedup 1.0000x reference)
#include <cuda_runtime.h>
#include <cstdint>

// Transitive closure of {0} under (left,right) == reference's 8192-step fixed
// point. One-CTA BFS-until-converged, atomic-free. R10-R12 showed the time is
// a SUM of prologue + loop + epilogue terms; this version attacks all three:
//   - TMA bulk copies (cp.async.bulk) load the 64KB child tables straight into
//     smem: no per-thread LDG pump, no register staging. Children are read
//     (LDS) once per node at expansion time only.
//   - 512 threads x 16 nodes: my reach state = ONE volatile LDS.128 per round;
//     16-warp barrier instead of 32 halves per-round issue skew.
//   - single sweep per round (multi-sweep proven useless in R10/R11),
//     __syncthreads_or convergence, idempotent byte stores (no atomics).

#define NNODES    8192
#define NTHREADS  512
#define NPT       16                      // nodes per thread
#define DONE_ALL  0x0101010101010101ull

// dynamic smem layout (bytes)
#define OFF_REACH 0                       // 8192  u8
#define OFF_L     8192                    // 32768 int32
#define OFF_R     40960                   // 32768 int32
#define OFF_MBAR  73728                   // 8     mbarrier
#define SMEM_SZ   73744

__global__ __launch_bounds__(NTHREADS, 1)
void DAGGenome_reach_kernel(const int* __restrict__ left,
                            const int* __restrict__ right,
                            float* __restrict__ out)
{
    extern __shared__ __align__(16) unsigned char smem[];
    const int tid  = threadIdx.x;
    const int base = tid * NPT;           // my nodes [base, base+16)

    unsigned char* reach = smem + OFF_REACH;
    const int* sL = (const int*)(smem + OFF_L);
    const int* sR = (const int*)(smem + OFF_R);

    const uint32_t sb   = (uint32_t)__cvta_generic_to_shared(smem);
    const uint32_t mbar = sb + OFF_MBAR;
    const uint32_t smy  = sb + OFF_REACH + base;   // my 16 reach bytes

    // --- init: zero reach (one STS.128/thread), init mbarrier ---
    ((uint4*)reach)[tid] = make_uint4(0, 0, 0, 0);
    if (tid == 0) {
        reach[0] = 1;                      // seed node 0 (same thread: ordered)
        asm volatile("mbarrier.init.shared.b64 [%0], %1;"
                     :: "r"(mbar), "r"(1) : "memory");
    }
    __syncthreads();                       // mbarrier visible to all

    // --- TMA bulk load of both child tables (64 KB) ---
    if (tid == 0) {
        asm volatile("mbarrier.arrive.expect_tx.shared.b64 _, [%0], %1;"
                     :: "r"(mbar), "r"(65536) : "memory");
        asm volatile("cp.async.bulk.shared::cta.global.mbarrier::complete_tx::bytes"
                     " [%0], [%1], %2, [%3];"
                     :: "r"(sb + OFF_L), "l"(left), "r"(32768), "r"(mbar)
                     : "memory");
        asm volatile("cp.async.bulk.shared::cta.global.mbarrier::complete_tx::bytes"
                     " [%0], [%1], %2, [%3];"
                     :: "r"(sb + OFF_R), "l"(right), "r"(32768), "r"(mbar)
                     : "memory");
    }
    // all threads wait for the data
    {
        uint32_t done_w;
        asm volatile(
            "{\n\t.reg .pred p;\n\t"
            "mbarrier.try_wait.parity.acquire.cta.shared::cta.b64 p, [%1], 0;\n\t"
            "selp.b32 %0, 1, 0, p;\n\t}"
            : "=r"(done_w) : "r"(mbar) : "memory");
        if (!done_w) {
            asm volatile(
                "{\n\t.reg .pred P1;\n\t"
                "W_%=: mbarrier.try_wait.parity.acquire.cta.shared::cta.b64 P1, [%0], 0, 0x989680;\n\t"
                "@P1 bra.uni D_%=;\n\t"
                "bra.uni W_%=;\n\t"
                "D_%=:\n\t}"
                :: "r"(mbar) : "memory");
        }
    }
    __syncthreads();

    // --- BFS to fixed point: one LDS.128 + BAR.RED per round ---
    unsigned long long done_lo = 0, done_hi = 0;

    for (;;) {
        int chg = 0;
        if ((done_lo & done_hi) != DONE_ALL) {
            unsigned long long v0, v1;
            asm volatile("ld.volatile.shared.v2.u64 {%0, %1}, [%2];"
                         : "=l"(v0), "=l"(v1) : "r"(smy) : "memory");
            const unsigned long long p0 = v0 & ~done_lo;
            const unsigned long long p1 = v1 & ~done_hi;
            if (p0 | p1) {
                chg = 1;
                done_lo |= p0;
                done_hi |= p1;
                #pragma unroll
                for (int j = 0; j < 8; j++) {
                    if (p0 & (1ull << (8 * j))) {
                        const int n = base + j;
                        const int a = sL[n]; if (a >= 0) reach[a] = 1;
                        const int b = sR[n]; if (b >= 0) reach[b] = 1;
                    }
                }
                #pragma unroll
                for (int j = 0; j < 8; j++) {
                    if (p1 & (1ull << (8 * j))) {
                        const int n = base + 8 + j;
                        const int a = sL[n]; if (a >= 0) reach[a] = 1;
                        const int b = sR[n]; if (b >= 0) reach[b] = 1;
                    }
                }
            }
        }
        if (!__syncthreads_or(chg)) break;
    }

    // --- output: my 16 bytes -> 16 floats, 4x STG.128 ---
    float4* op = (float4*)(out + base);
    #pragma unroll
    for (int q = 0; q < 4; q++) {
        float4 o;
        o.x = reach[base + 4 * q + 0] ? 1.0f : 0.0f;
        o.y = reach[base + 4 * q + 1] ? 1.0f : 0.0f;
        o.z = reach[base + 4 * q + 2] ? 1.0f : 0.0f;
        o.w = reach[base + 4 * q + 3] ? 1.0f : 0.0f;
        op[q] = o;
    }
}

extern "C" void kernel_launch(void* const* d_in, const int* in_sizes, int n_in,
                              void* d_out, int out_size)
{
    const int* left  = (const int*)d_in[1];
    const int* right = (const int*)d_in[2];
    float* out = (float*)d_out;

    static bool attr_set = false;
    if (!attr_set) {
        cudaFuncSetAttribute(DAGGenome_reach_kernel,
                             cudaFuncAttributeMaxDynamicSharedMemorySize,
                             SMEM_SZ);
        attr_set = true;
    }

    DAGGenome_reach_kernel<<<1, NTHREADS, SMEM_SZ>>>(left, right, out);
}

// round 14
// speedup vs baseline: 1.4117x; 1.4117x over previous
#include <cuda_runtime.h>

// Transitive closure of {0} under (left,right) == reference's 8192-step fixed
// point. One-CTA BFS-until-converged, atomic-free.
// R13 post-mortem: loop cost = rounds x (barrier + skew), rounds >> expected
// (long BFS tail), and any LDS on the expansion path is poison.
// This round: TWO BFS LEVELS PER ROUND with ALL indices in REGISTERS:
//   - prologue stages int16 child tables in smem, gathers grandchildren into
//     packed int16 registers, then the tables are dead
//   - expansion sets children + grandchildren bytes straight from registers
//     (no LDS before any STS) -> rounds ~= depth/2 + 1 at R11's per-round cost
//   - loop body = R11's best shape: 1 volatile LDS.64, byte-mask done,
//     __syncthreads_or, single sweep, idempotent byte stores

#define NNODES    8192
#define NTHREADS  1024
#define DONE_ALL  0x0101010101010101ull

__global__ __launch_bounds__(NTHREADS, 1)
void DAGGenome_reach_kernel(const int* __restrict__ left,
                            const int* __restrict__ right,
                            float* __restrict__ out)
{
    __shared__ __align__(16) unsigned char reach8[NNODES];
    __shared__ __align__(16) short sl[NNODES];    // staging only (dead after prologue)
    __shared__ __align__(16) short sr[NNODES];

    const int tid = threadIdx.x;

    // --- load my 8 nodes' children (coalesced int4) ---
    const int4* lp = (const int4*)left  + tid * 2;
    const int4* rp = (const int4*)right + tid * 2;
    const int4 l0 = lp[0], l1 = lp[1];
    const int4 r0 = rp[0], r1 = rp[1];
    const int cl[8] = { l0.x, l0.y, l0.z, l0.w, l1.x, l1.y, l1.z, l1.w };
    const int cr[8] = { r0.x, r0.y, r0.z, r0.w, r1.x, r1.y, r1.z, r1.w };

    // --- stage child tables as int16 in smem (for grandchild gathers) ---
    uint4 pl, pr;
    pl.x = (l0.x & 0xffff) | (l0.y << 16);
    pl.y = (l0.z & 0xffff) | (l0.w << 16);
    pl.z = (l1.x & 0xffff) | (l1.y << 16);
    pl.w = (l1.z & 0xffff) | (l1.w << 16);
    pr.x = (r0.x & 0xffff) | (r0.y << 16);
    pr.y = (r0.z & 0xffff) | (r0.w << 16);
    pr.z = (r1.x & 0xffff) | (r1.y << 16);
    pr.w = (r1.z & 0xffff) | (r1.w << 16);
    ((uint4*)sl)[tid] = pl;
    ((uint4*)sr)[tid] = pr;

    ((unsigned long long*)reach8)[tid] = 0ull;    // zero byte map
    if (tid == 0) reach8[0] = 1;                  // seed (same thread: ordered)
    __syncthreads();

    // --- gather grandchildren into packed int16 registers ---
    // ga[j] = (left[cl[j]] , right[cl[j]]),  gb[j] = (left[cr[j]] , right[cr[j]])
    unsigned int ga[8], gb[8];
    #pragma unroll
    for (int j = 0; j < 8; j++) {
        const int a = cl[j];
        ga[j] = (a >= 0)
              ? ((unsigned short)sl[a] | ((unsigned int)(unsigned short)sr[a] << 16))
              : 0xffffffffu;
        const int b = cr[j];
        gb[j] = (b >= 0)
              ? ((unsigned short)sl[b] | ((unsigned int)(unsigned short)sr[b] << 16))
              : 0xffffffffu;
    }

    volatile unsigned long long* vmy =
        (volatile unsigned long long*)reach8 + tid;   // my 8 bytes
    volatile unsigned char* vr = (volatile unsigned char*)reach8;

    unsigned long long done64 = 0;   // 0x01 byte per already-expanded node
    __syncthreads();                 // gathers done before loop (tables now dead)

    // --- BFS, 2 levels per round, one LDS.64 + BAR.RED per round ---
    for (;;) {
        int chg = 0;

        if (done64 != DONE_ALL) {
            const unsigned long long pending = (*vmy) & ~done64;
            if (pending) {
                chg = 1;
                done64 |= pending;
                #pragma unroll
                for (int j = 0; j < 8; j++) {
                    if (pending & (1ull << (8 * j))) {
                        const int a = cl[j];
                        if (a >= 0) {
                            vr[a] = 1;
                            const short g0 = (short)(ga[j] & 0xffff);
                            const short g1 = (short)(ga[j] >> 16);
                            if (g0 >= 0) vr[g0] = 1;
                            if (g1 >= 0) vr[g1] = 1;
                        }
                        const int b = cr[j];
                        if (b >= 0) {
                            vr[b] = 1;
                            const short h0 = (short)(gb[j] & 0xffff);
                            const short h1 = (short)(gb[j] >> 16);
                            if (h0 >= 0) vr[h0] = 1;
                            if (h1 >= 0) vr[h1] = 1;
                        }
                    }
                }
            }
        }

        if (!__syncthreads_or(chg)) break;
    }

    // --- float32 output: my 8 bytes -> 2x float4 stores ---
    const unsigned long long v = *vmy;
    float4 o0, o1;
    o0.x = (v & 0x01ull)      ? 1.0f : 0.0f;
    o0.y = (v & (1ull << 8))  ? 1.0f : 0.0f;
    o0.z = (v & (1ull << 16)) ? 1.0f : 0.0f;
    o0.w = (v & (1ull << 24)) ? 1.0f : 0.0f;
    o1.x = (v & (1ull << 32)) ? 1.0f : 0.0f;
    o1.y = (v & (1ull << 40)) ? 1.0f : 0.0f;
    o1.z = (v & (1ull << 48)) ? 1.0f : 0.0f;
    o1.w = (v & (1ull << 56)) ? 1.0f : 0.0f;
    float4* op = (float4*)out + tid * 2;
    op[0] = o0;
    op[1] = o1;
}

extern "C" void kernel_launch(void* const* d_in, const int* in_sizes, int n_in,
                              void* d_out, int out_size)
{
    const int* left  = (const int*)d_in[1];
    const int* right = (const int*)d_in[2];
    float* out = (float*)d_out;

    DAGGenome_reach_kernel<<<1, NTHREADS>>>(left, right, out);
}

// round 15
// speedup vs baseline: 1.5802x; 1.1194x over previous
#include <cuda_runtime.h>

// Transitive closure of {0} under (left,right) == reference's 8192-step fixed
// point. One-CTA BFS-until-converged, atomic-free.
// R10-R14 post-mortem: at the (low, uncontrolled) clock this kernel runs at,
// the loop dominates and its per-round cost is the SERIAL BRANCHY expansion
// chain, not the LDS or barrier. This round flattens expansion to branchless
// predicated stores:
//   - prologue precomputes per-child smem byte indices, leaves -> DUMMY pad
//   - expansion per j: pending-bit ISETP + 2 SEL + 2 STS, all 8 j independent,
//     zero branches, zero >=0 tests, no dependency chain (STS fire-and-forget)
//   - loop shape = R11's best: 1 volatile LDS.64, byte-mask done,
//     __syncthreads_or, single sweep, idempotent byte stores

#define NNODES    8192
#define NTHREADS  1024
#define DUMMY     NNODES                     // pad slot absorbing leaf writes
#define DONE_ALL  0x0101010101010101ull

__global__ __launch_bounds__(NTHREADS, 1)
void DAGGenome_reach_kernel(const int* __restrict__ left,
                            const int* __restrict__ right,
                            float* __restrict__ out)
{
    __shared__ __align__(16) unsigned char reach8[NNODES + 16];  // +pad (DUMMY)

    const int tid = threadIdx.x;

    // --- load my 8 nodes' children (coalesced int4) ---
    const int4* lp = (const int4*)left  + tid * 2;
    const int4* rp = (const int4*)right + tid * 2;
    const int4 l0 = lp[0], l1 = lp[1];
    const int4 r0 = rp[0], r1 = rp[1];
    const int cl[8] = { l0.x, l0.y, l0.z, l0.w, l1.x, l1.y, l1.z, l1.w };
    const int cr[8] = { r0.x, r0.y, r0.z, r0.w, r1.x, r1.y, r1.z, r1.w };

    // --- precompute store indices: leaf (-1) -> DUMMY pad byte ---
    unsigned int offL[8], offR[8];
    #pragma unroll
    for (int j = 0; j < 8; j++) {
        offL[j] = (cl[j] >= 0) ? (unsigned int)cl[j] : (unsigned int)DUMMY;
        offR[j] = (cr[j] >= 0) ? (unsigned int)cr[j] : (unsigned int)DUMMY;
    }

    // --- init byte map (one u64 store per thread) + pad, seed node 0 ---
    ((unsigned long long*)reach8)[tid] = 0ull;
    if (tid < 2) ((unsigned long long*)(reach8 + NNODES))[tid] = 0ull;
    if (tid == 0) reach8[0] = 1;     // same thread zeroed this word: ordered

    volatile unsigned long long* vmy =
        (volatile unsigned long long*)reach8 + tid;   // my 8 bytes
    volatile unsigned char* vr = (volatile unsigned char*)reach8;

    unsigned long long done64 = 0;   // 0x01 byte per already-expanded node
    __syncthreads();

    // --- BFS to fixed point: LDS.64 + branchless expansion + BAR.RED ---
    for (;;) {
        int chg = 0;

        if (done64 != DONE_ALL) {
            const unsigned long long pending = (*vmy) & ~done64;
            if (pending) {
                chg = 1;
                done64 |= pending;
                // branchless: select real addr or DUMMY per pending bit,
                // 16 independent STS, no chain
                #pragma unroll
                for (int j = 0; j < 8; j++) {
                    const bool p = (pending >> (8 * j)) & 1u;
                    const unsigned int a = p ? offL[j] : (unsigned int)DUMMY;
                    const unsigned int b = p ? offR[j] : (unsigned int)DUMMY;
                    vr[a] = 1;
                    vr[b] = 1;
                }
            }
        }

        if (!__syncthreads_or(chg)) break;
    }

    // --- float32 output: my 8 bytes -> 2x float4 stores ---
    const unsigned long long v = *vmy;
    float4 o0, o1;
    o0.x = (v & 0x01ull)      ? 1.0f : 0.0f;
    o0.y = (v & (1ull << 8))  ? 1.0f : 0.0f;
    o0.z = (v & (1ull << 16)) ? 1.0f : 0.0f;
    o0.w = (v & (1ull << 24)) ? 1.0f : 0.0f;
    o1.x = (v & (1ull << 32)) ? 1.0f : 0.0f;
    o1.y = (v & (1ull << 40)) ? 1.0f : 0.0f;
    o1.z = (v & (1ull << 48)) ? 1.0f : 0.0f;
    o1.w = (v & (1ull << 56)) ? 1.0f : 0.0f;
    float4* op = (float4*)out + tid * 2;
    op[0] = o0;
    op[1] = o1;
}

extern "C" void kernel_launch(void* const* d_in, const int* in_sizes, int n_in,
                              void* d_out, int out_size)
{
    const int* left  = (const int*)d_in[1];
    const int* right = (const int*)d_in[2];
    float* out = (float*)d_out;

    DAGGenome_reach_kernel<<<1, NTHREADS>>>(left, right, out);
}

// round 16
// speedup vs baseline: 1.6072x; 1.0171x over previous
#include <cuda_runtime.h>
#include <cstdint>

// Transitive closure of {0} under (left,right) == reference's 8192-step fixed
// point. One-CTA BFS-until-converged, atomic-free.
// R10-R15 showed per-round cost is dominated by 32-warp barrier arrival skew,
// not the body. This round:
//   - BFS runs on 512 threads (16 warps, 16 nodes each, one LDS.128 scan);
//     the other 512 threads SLEEP on named barrier 1 (zero issue pollution)
//   - convergence via bar.red.or.pred on named barrier 2 (count 512)
//   - packed (L,R) child offsets exchanged via smem once in prologue, held in
//     16 regs per BFS thread -> expansion is SEL+STS only, no LDS on the path
//   - node 0 pre-expanded in prologue (saves one round)
//   - prologue/epilogue stay 1024-wide (R15 shape)

#define NNODES    8192
#define NTHREADS  1024
#define NBFS      512
#define DUMMY     NNODES
#define DONE_ALL  0x0101010101010101ull

__global__ __launch_bounds__(NTHREADS, 1)
void DAGGenome_reach_kernel(const int* __restrict__ left,
                            const int* __restrict__ right,
                            float* __restrict__ out)
{
    __shared__ __align__(16) unsigned char reach8[NNODES + 16];   // +DUMMY pad
    __shared__ __align__(16) unsigned int  offpk[NNODES];         // (L | R<<16)

    const int tid = threadIdx.x;

    // --- prologue (1024-wide): load my 8 nodes' children, pack offsets ---
    const int4* lp = (const int4*)left  + tid * 2;
    const int4* rp = (const int4*)right + tid * 2;
    const int4 l0 = lp[0], l1 = lp[1];
    const int4 r0 = rp[0], r1 = rp[1];
    const int cl[8] = { l0.x, l0.y, l0.z, l0.w, l1.x, l1.y, l1.z, l1.w };
    const int cr[8] = { r0.x, r0.y, r0.z, r0.w, r1.x, r1.y, r1.z, r1.w };

    unsigned int pk[8];
    #pragma unroll
    for (int j = 0; j < 8; j++) {
        const unsigned int a = (cl[j] >= 0) ? (unsigned int)cl[j] : (unsigned int)DUMMY;
        const unsigned int b = (cr[j] >= 0) ? (unsigned int)cr[j] : (unsigned int)DUMMY;
        pk[j] = a | (b << 16);
    }
    ((uint4*)offpk)[tid * 2 + 0] = make_uint4(pk[0], pk[1], pk[2], pk[3]);
    ((uint4*)offpk)[tid * 2 + 1] = make_uint4(pk[4], pk[5], pk[6], pk[7]);

    ((unsigned long long*)reach8)[tid] = 0ull;
    if (tid < 2) ((unsigned long long*)(reach8 + NNODES))[tid] = 0ull;
    if (tid == 0) {
        reach8[0] = 1;                       // seed
        if (cl[0] >= 0) reach8[cl[0]] = 1;   // pre-expand node 0 (level 1)
        if (cr[0] >= 0) reach8[cr[0]] = 1;
    }
    __syncthreads();

    if (tid >= NBFS) {
        // --- sleepers: wait for BFS convergence on named barrier 1 ---
        asm volatile("bar.sync 1, %0;" :: "r"(NTHREADS) : "memory");
    } else {
        // --- BFS thread: owns nodes [16*tid, 16*tid+16) ---
        const int base = tid * 16;
        const uint4 q0 = ((const uint4*)offpk)[tid * 4 + 0];
        const uint4 q1 = ((const uint4*)offpk)[tid * 4 + 1];
        const uint4 q2 = ((const uint4*)offpk)[tid * 4 + 2];
        const uint4 q3 = ((const uint4*)offpk)[tid * 4 + 3];
        const unsigned int opk[16] = { q0.x, q0.y, q0.z, q0.w,
                                       q1.x, q1.y, q1.z, q1.w,
                                       q2.x, q2.y, q2.z, q2.w,
                                       q3.x, q3.y, q3.z, q3.w };

        const uint32_t smy =
            (uint32_t)__cvta_generic_to_shared(reach8) + base;
        volatile unsigned char* vr = (volatile unsigned char*)reach8;

        unsigned long long done0 = (tid == 0) ? 0x01ull : 0ull;  // node 0 done
        unsigned long long done1 = 0ull;

        for (;;) {
            int chg = 0;

            if ((done0 & done1) != DONE_ALL) {
                unsigned long long v0, v1;
                asm volatile("ld.volatile.shared.v2.u64 {%0, %1}, [%2];"
                             : "=l"(v0), "=l"(v1) : "r"(smy) : "memory");
                const unsigned long long p0 = v0 & ~done0;
                const unsigned long long p1 = v1 & ~done1;
                if (p0) {
                    chg = 1; done0 |= p0;
                    #pragma unroll
                    for (int j = 0; j < 8; j++) {
                        const bool p = (p0 >> (8 * j)) & 1u;
                        const unsigned int w = opk[j];
                        const unsigned int a = p ? (w & 0xffffu) : (unsigned int)DUMMY;
                        const unsigned int b = p ? (w >> 16)     : (unsigned int)DUMMY;
                        vr[a] = 1;
                        vr[b] = 1;
                    }
                }
                if (p1) {
                    chg = 1; done1 |= p1;
                    #pragma unroll
                    for (int j = 0; j < 8; j++) {
                        const bool p = (p1 >> (8 * j)) & 1u;
                        const unsigned int w = opk[8 + j];
                        const unsigned int a = p ? (w & 0xffffu) : (unsigned int)DUMMY;
                        const unsigned int b = p ? (w >> 16)     : (unsigned int)DUMMY;
                        vr[a] = 1;
                        vr[b] = 1;
                    }
                }
            }

            // convergence across the 512 BFS threads only (named barrier 2)
            unsigned int any;
            asm volatile(
                "{\n\t.reg .pred p, q;\n\t"
                "setp.ne.u32 p, %1, 0;\n\t"
                "bar.red.or.pred q, 2, %2, p;\n\t"
                "selp.u32 %0, 1, 0, q;\n\t}"
                : "=r"(any) : "r"(chg), "r"(NBFS) : "memory");
            if (!any) break;
        }

        // release the sleepers
        asm volatile("bar.sync 1, %0;" :: "r"(NTHREADS) : "memory");
    }

    // --- epilogue (1024-wide): my 8 bytes -> 2x float4 stores ---
    const unsigned long long v = ((volatile unsigned long long*)reach8)[tid];
    float4 o0, o1;
    o0.x = (v & 0x01ull)      ? 1.0f : 0.0f;
    o0.y = (v & (1ull << 8))  ? 1.0f : 0.0f;
    o0.z = (v & (1ull << 16)) ? 1.0f : 0.0f;
    o0.w = (v & (1ull << 24)) ? 1.0f : 0.0f;
    o1.x = (v & (1ull << 32)) ? 1.0f : 0.0f;
    o1.y = (v & (1ull << 40)) ? 1.0f : 0.0f;
    o1.z = (v & (1ull << 48)) ? 1.0f : 0.0f;
    o1.w = (v & (1ull << 56)) ? 1.0f : 0.0f;
    float4* op = (float4*)out + tid * 2;
    op[0] = o0;
    op[1] = o1;
}

extern "C" void kernel_launch(void* const* d_in, const int* in_sizes, int n_in,
                              void* d_out, int out_size)
{
    const int* left  = (const int*)d_in[1];
    const int* right = (const int*)d_in[2];
    float* out = (float*)d_out;

    DAGGenome_reach_kernel<<<1, NTHREADS>>>(left, right, out);
}